// round 1
// baseline (speedup 1.0000x reference)
#include <cuda_runtime.h>

#define NNODES 4096
#define NEDGES 32768
#define NSC 48
#define NVC 16
#define NEF 128
#define WNUM 4096
#define BN_EPS 1e-5f
#define INV_SQRT3 0.57735026918962576f
#define ALPHA 0.125f

// ---------------- static device scratch (no allocations allowed) ----------------
__device__ float g_H[NEDGES * NEF];     // H = relu(edge_attr @ W1 + b1), [e][kk]
__device__ float g_W2p[WNUM * NEF];     // fc_w2 transposed: [j][kk]
__device__ float g_accum[NNODES * 96];  // node_attr + segment_sum(msg)
__device__ float g_mean[NSC];
__device__ float g_rs[NSC];
__device__ float g_rsv[NVC];
__device__ int g_src[NEDGES];
__device__ int g_dst[NEDGES];
__device__ int g_mode;                  // 1 = edge_index stored as int32, 0 = int64

// ---------------- edge_index dtype detection + conversion ----------------
__global__ void k_detect_idx(const int* __restrict__ raw) {
    __shared__ int flag;
    int t = threadIdx.x;
    if (t == 0) flag = 0;
    __syncthreads();
    // If data is int64 (little-endian, values in [0,4096)), every odd 32-bit word is 0.
    for (int i = t; i < 2048; i += 256) {
        if (raw[2 * i + 1] != 0) flag = 1;
    }
    __syncthreads();
    if (t == 0) g_mode = flag;
}

__global__ void k_convert_idx(const int* __restrict__ raw) {
    int e = blockIdx.x * 256 + threadIdx.x;
    if (e >= NEDGES) return;
    if (g_mode) {  // int32 layout
        g_src[e] = raw[e];
        g_dst[e] = raw[NEDGES + e];
    } else {       // int64 layout: low word at even position
        g_src[e] = raw[2 * e];
        g_dst[e] = raw[2 * (NEDGES + e)];
    }
}

// ---------------- W2 transpose: [kk][j] -> [j][kk] ----------------
__global__ void k_transpose_w2(const float* __restrict__ w2) {
    __shared__ float tile[32][33];
    int j0 = blockIdx.x * 32;
    int k0 = blockIdx.y * 32;
    int tx = threadIdx.x, ty = threadIdx.y;
#pragma unroll
    for (int r = ty; r < 32; r += 8)
        tile[r][tx] = w2[(size_t)(k0 + r) * WNUM + j0 + tx];
    __syncthreads();
#pragma unroll
    for (int r = ty; r < 32; r += 8)
        g_W2p[(size_t)(j0 + r) * NEF + k0 + tx] = tile[tx][r];
}

// ---------------- Stage A: H = relu(edge_attr @ W1 + b1) ----------------
__global__ __launch_bounds__(256) void k_stage_a(const float* __restrict__ ea,
                                                 const float* __restrict__ w1,
                                                 const float* __restrict__ b1) {
    __shared__ float As[32][65];   // [kk][e], padded
    __shared__ float Ws[32][128];  // [kk][col]
    int t = threadIdx.x;
    int tx = t & 31, ty = t >> 5;  // tx: col/4, ty: e-group
    int e0 = blockIdx.x * 64;
    float acc[8][4];
#pragma unroll
    for (int i = 0; i < 8; ++i)
#pragma unroll
        for (int j = 0; j < 4; ++j) acc[i][j] = 0.f;

    for (int k0 = 0; k0 < NEF; k0 += 32) {
        for (int idx = t; idx < 64 * 32; idx += 256) {
            int e = idx >> 5, kk = idx & 31;
            As[kk][e] = ea[(size_t)(e0 + e) * NEF + k0 + kk];
        }
        for (int idx = t; idx < 32 * 128; idx += 256) {
            int kk = idx >> 7, cc = idx & 127;
            Ws[kk][cc] = w1[(size_t)(k0 + kk) * NEF + cc];
        }
        __syncthreads();
#pragma unroll 8
        for (int kk = 0; kk < 32; ++kk) {
            float4 b = *reinterpret_cast<const float4*>(&Ws[kk][tx * 4]);
#pragma unroll
            for (int i = 0; i < 8; ++i) {
                float a = As[kk][ty * 8 + i];
                acc[i][0] = fmaf(a, b.x, acc[i][0]);
                acc[i][1] = fmaf(a, b.y, acc[i][1]);
                acc[i][2] = fmaf(a, b.z, acc[i][2]);
                acc[i][3] = fmaf(a, b.w, acc[i][3]);
            }
        }
        __syncthreads();
    }
    float4 bias = *reinterpret_cast<const float4*>(&b1[tx * 4]);
#pragma unroll
    for (int i = 0; i < 8; ++i) {
        float4 o;
        o.x = fmaxf(acc[i][0] + bias.x, 0.f);
        o.y = fmaxf(acc[i][1] + bias.y, 0.f);
        o.z = fmaxf(acc[i][2] + bias.z, 0.f);
        o.w = fmaxf(acc[i][3] + bias.w, 0.f);
        *reinterpret_cast<float4*>(&g_H[(size_t)(e0 + ty * 8 + i) * NEF + tx * 4]) = o;
    }
}

// ---------------- accumulator init with residual ----------------
__global__ void k_init_accum(const float* __restrict__ na) {
    int idx = blockIdx.x * 256 + threadIdx.x;
    if (idx < NNODES * 96) g_accum[idx] = na[idx];
}

// ---------------- Stage B: fused GEMM (H @ W2) + dlrelu + tensor product + scatter ----------------
struct SmemB {
    float Hs[NEF][65];     // [kk][e], padded
    float coefS[64][65];   // i<48: xs_i*ss ; i>=48: dot_{i-48}
    float xss[64][49];     // xs
    float xvs[64][49];     // xv flattened 3*i+m
    float svs[64][3];
    float sss[64];
    int dsts[64];
    int srcs[64];
};

__device__ __forceinline__ float dlrelu(float x) {
    return (fabsf(x) <= 10.f) ? x : 0.01f * x;
}

// c[ti] = dot(H[e][:], W2p_row(j0 + ti*colstride)[:]) over kk=0..127
__device__ __forceinline__ void dot8(const float* __restrict__ wb, int wstride,
                                     const float* hcol, float c[8]) {
#pragma unroll
    for (int ti = 0; ti < 8; ++ti) c[ti] = 0.f;
#pragma unroll 4
    for (int kkc = 0; kkc < 32; ++kkc) {
        float h0 = hcol[(4 * kkc + 0) * 65];
        float h1 = hcol[(4 * kkc + 1) * 65];
        float h2 = hcol[(4 * kkc + 2) * 65];
        float h3 = hcol[(4 * kkc + 3) * 65];
#pragma unroll
        for (int ti = 0; ti < 8; ++ti) {
            float4 w = __ldg(reinterpret_cast<const float4*>(wb + (size_t)ti * wstride) + kkc);
            c[ti] = fmaf(h0, w.x, c[ti]);
            c[ti] = fmaf(h1, w.y, c[ti]);
            c[ti] = fmaf(h2, w.z, c[ti]);
            c[ti] = fmaf(h3, w.w, c[ti]);
        }
    }
}

extern __shared__ char smem_raw[];

__global__ __launch_bounds__(256, 2) void k_stage_b(const float* __restrict__ na,
                                                    const float* __restrict__ sh,
                                                    const float* __restrict__ b2) {
    SmemB& sm = *reinterpret_cast<SmemB*>(smem_raw);
    int t = threadIdx.x;
    int e0 = blockIdx.x * 64;

    if (t < 64) {
        int e = e0 + t;
        sm.srcs[t] = g_src[e];
        sm.dsts[t] = g_dst[e];
        float4 shv = __ldg(reinterpret_cast<const float4*>(sh) + e);
        sm.sss[t] = shv.x;
        sm.svs[t][0] = shv.y;
        sm.svs[t][1] = shv.z;
        sm.svs[t][2] = shv.w;
    }
    __syncthreads();
    // gather node_attr[src]
    for (int idx = t; idx < 64 * 96; idx += 256) {
        int e = idx / 96, c = idx % 96;
        float v = na[(size_t)sm.srcs[e] * 96 + c];
        if (c < 48) sm.xss[e][c] = v;
        else sm.xvs[e][c - 48] = v;
    }
    // H tile
    for (int idx = t; idx < 64 * NEF; idx += 256) {
        int e = idx >> 7, kk = idx & 127;
        sm.Hs[kk][e] = g_H[(size_t)(e0 + e) * NEF + kk];
    }
    __syncthreads();
    // scalar-path coefficients
    for (int idx = t; idx < 64 * 64; idx += 256) {
        int e = idx >> 6, i = idx & 63;
        float v;
        if (i < 48) {
            v = sm.xss[e][i] * sm.sss[e];
        } else {
            int i2 = i - 48;
            v = INV_SQRT3 * (sm.xvs[e][3 * i2 + 0] * sm.svs[e][0]
                           + sm.xvs[e][3 * i2 + 1] * sm.svs[e][1]
                           + sm.xvs[e][3 * i2 + 2] * sm.svs[e][2]);
        }
        sm.coefS[e][i] = v;
    }
    __syncthreads();

    int el = t & 63;
    int kg = t >> 6;
    const float* hcol = &sm.Hs[0][el];
    float* arow = g_accum + (size_t)sm.dsts[el] * 96;

    // ---- scalar outputs: out_s[k], k = kg + 4u ----
#pragma unroll 1
    for (int u = 0; u < 12; ++u) {
        int k = kg + 4 * u;
        float acc = 0.f;
#pragma unroll 1
        for (int i0 = 0; i0 < 64; i0 += 8) {
            float c[8];
            const float* wb = g_W2p + (size_t)(i0 * 48 + k) * NEF;
            dot8(wb, 48 * NEF, hcol, c);
#pragma unroll
            for (int ti = 0; ti < 8; ++ti) {
                int j = (i0 + ti) * 48 + k;
                float x = c[ti] + __ldg(b2 + j);
                acc = fmaf(sm.coefS[el][i0 + ti], dlrelu(x), acc);
            }
        }
        atomicAdd(arow + k, ALPHA * acc);
    }

    // ---- vector outputs: out_v[k][m], k = kg + 4u ----
#pragma unroll 1
    for (int u = 0; u < 4; ++u) {
        int k = kg + 4 * u;
        float t1 = 0.f, tv0 = 0.f, tv1 = 0.f, tv2 = 0.f;
#pragma unroll 1
        for (int i0 = 0; i0 < 48; i0 += 8) {  // w_sv block
            float c[8];
            const float* wb = g_W2p + (size_t)(3072 + i0 * 16 + k) * NEF;
            dot8(wb, 16 * NEF, hcol, c);
#pragma unroll
            for (int ti = 0; ti < 8; ++ti) {
                int j = 3072 + (i0 + ti) * 16 + k;
                float x = c[ti] + __ldg(b2 + j);
                t1 = fmaf(sm.xss[el][i0 + ti], dlrelu(x), t1);
            }
        }
        {  // w_vv block (16 i values = 2 chunks)
#pragma unroll 1
            for (int i0 = 0; i0 < 16; i0 += 8) {
                float c[8];
                const float* wb = g_W2p + (size_t)(3840 + i0 * 16 + k) * NEF;
                dot8(wb, 16 * NEF, hcol, c);
#pragma unroll
                for (int ti = 0; ti < 8; ++ti) {
                    int i = i0 + ti;
                    int j = 3840 + i * 16 + k;
                    float w = dlrelu(c[ti] + __ldg(b2 + j));
                    tv0 = fmaf(sm.xvs[el][3 * i + 0], w, tv0);
                    tv1 = fmaf(sm.xvs[el][3 * i + 1], w, tv1);
                    tv2 = fmaf(sm.xvs[el][3 * i + 2], w, tv2);
                }
            }
        }
        float ss = sm.sss[el];
        atomicAdd(arow + 48 + 3 * k + 0, ALPHA * fmaf(t1, sm.svs[el][0], ss * tv0));
        atomicAdd(arow + 48 + 3 * k + 1, ALPHA * fmaf(t1, sm.svs[el][1], ss * tv1));
        atomicAdd(arow + 48 + 3 * k + 2, ALPHA * fmaf(t1, sm.svs[el][2], ss * tv2));
    }
}

// ---------------- batchnorm statistics ----------------
__global__ __launch_bounds__(256) void k_stats(const float* __restrict__ bnw) {
    __shared__ float r1[256], r2[256];
    int b = blockIdx.x, t = threadIdx.x;
    float s1 = 0.f, s2 = 0.f;
    if (b < NSC) {
        for (int n = t; n < NNODES; n += 256) {
            float x = g_accum[(size_t)n * 96 + b];
            s1 += x;
            s2 += x * x;
        }
    } else {
        int k = b - NSC;
        for (int n = t; n < NNODES; n += 256) {
            const float* p = &g_accum[(size_t)n * 96 + 48 + 3 * k];
            float x0 = p[0], x1 = p[1], x2 = p[2];
            s2 += x0 * x0 + x1 * x1 + x2 * x2;
        }
    }
    r1[t] = s1;
    r2[t] = s2;
    __syncthreads();
    for (int off = 128; off > 0; off >>= 1) {
        if (t < off) {
            r1[t] += r1[t + off];
            r2[t] += r2[t + off];
        }
        __syncthreads();
    }
    if (t == 0) {
        if (b < NSC) {
            float mean = r1[0] / (float)NNODES;
            float var = r2[0] / (float)NNODES - mean * mean;
            g_mean[b] = mean;
            g_rs[b] = rsqrtf(var + BN_EPS) * bnw[b];
        } else {
            int k = b - NSC;
            float vn = r2[0] / (3.0f * (float)NNODES);
            g_rsv[k] = rsqrtf(vn + BN_EPS) * bnw[NSC + k];
        }
    }
}

// ---------------- final normalize ----------------
__global__ void k_final(const float* __restrict__ bnb, float* __restrict__ out) {
    int idx = blockIdx.x * 256 + threadIdx.x;
    if (idx >= NNODES * 96) return;
    int c = idx % 96;
    float x = g_accum[idx];
    float o;
    if (c < NSC) {
        o = (x - g_mean[c]) * g_rs[c] + bnb[c];
    } else {
        int k = (c - 48) / 3;
        o = x * g_rsv[k];
    }
    out[idx] = o;
}

// ---------------- launch ----------------
extern "C" void kernel_launch(void* const* d_in, const int* in_sizes, int n_in,
                              void* d_out, int out_size) {
    const float* node_attr = (const float*)d_in[0];
    const int* eidx_raw    = (const int*)d_in[1];   // int32 or int64 — detected on device
    const float* edge_attr = (const float*)d_in[2];
    const float* edge_sh   = (const float*)d_in[3];
    const float* fc_w1     = (const float*)d_in[4];
    const float* fc_b1     = (const float*)d_in[5];
    const float* fc_w2     = (const float*)d_in[6];
    const float* fc_b2     = (const float*)d_in[7];
    const float* bn_weight = (const float*)d_in[8];
    const float* bn_bias   = (const float*)d_in[9];
    float* out = (float*)d_out;

    cudaFuncSetAttribute(k_stage_b, cudaFuncAttributeMaxDynamicSharedMemorySize,
                         (int)sizeof(SmemB));

    k_detect_idx<<<1, 256>>>(eidx_raw);
    k_convert_idx<<<(NEDGES + 255) / 256, 256>>>(eidx_raw);
    k_transpose_w2<<<dim3(WNUM / 32, NEF / 32), dim3(32, 8)>>>(fc_w2);
    k_stage_a<<<NEDGES / 64, 256>>>(edge_attr, fc_w1, fc_b1);
    k_init_accum<<<(NNODES * 96 + 255) / 256, 256>>>(node_attr);
    k_stage_b<<<NEDGES / 64, 256, sizeof(SmemB)>>>(node_attr, edge_sh, fc_b2);
    k_stats<<<NSC + NVC, 256>>>(bn_weight);
    k_final<<<(NNODES * 96 + 255) / 256, 256>>>(bn_bias, out);
}